// round 1
// baseline (speedup 1.0000x reference)
#include <cuda_runtime.h>
#include <math.h>

#define BB 2
#define LL 2048
#define DM 1024
#define DI 2048
#define DS 16
#define DR 64
#define NXD 96          // DR + 2*DS
#define MM (BB*LL)      // 4096

// ---------------- scratch (device globals: alloc-free) ----------------
__device__ float g_xz[(size_t)MM * (2*DI)];   // in_proj output: [xin | z]
__device__ float g_xc[(size_t)MM * DI];       // conv+silu output
__device__ float g_xdbl[(size_t)MM * NXD];    // [dt(64) | B(16) | C(16)]
__device__ float g_delta[(size_t)MM * DI];    // softplus(dt @ W + b)
__device__ float g_y[(size_t)MM * DI];        // gated scan output
__device__ float g_o1[(size_t)MM * DM];       // ssm out_proj output

// ---------------- generic SGEMM: C = A(MxK,row,lda) * B(NxK,row,ldb)^T ----------------
// EPI: 0=none, 1=softplus(x+bias), 2=silu(x+bias)
template<int EPI>
__global__ __launch_bounds__(256, 2)
void sgemm_nt(const float* __restrict__ A, int lda,
              const float* __restrict__ Bm, int ldb,
              float* __restrict__ C, int ldc,
              int N, int K, const float* __restrict__ bias)
{
    __shared__ float As[16][128];
    __shared__ float Bs[16][128];
    const int tid = threadIdx.x;
    const int bm = blockIdx.y * 128;
    const int bn = blockIdx.x * 128;
    const int tx = tid & 15;
    const int ty = tid >> 4;
    const int lrow = tid >> 2;          // 0..63
    const int lcol = (tid & 3) << 2;    // 0,4,8,12

    float acc[8][8];
    #pragma unroll
    for (int i = 0; i < 8; i++)
        #pragma unroll
        for (int j = 0; j < 8; j++) acc[i][j] = 0.f;

    for (int k0 = 0; k0 < K; k0 += 16) {
        #pragma unroll
        for (int r = 0; r < 2; r++) {
            int row = lrow + r * 64;
            const float4 v = *reinterpret_cast<const float4*>(
                &A[(size_t)(bm + row) * lda + k0 + lcol]);
            As[lcol + 0][row] = v.x; As[lcol + 1][row] = v.y;
            As[lcol + 2][row] = v.z; As[lcol + 3][row] = v.w;
        }
        #pragma unroll
        for (int r = 0; r < 2; r++) {
            int row = lrow + r * 64;
            float4 v = make_float4(0.f, 0.f, 0.f, 0.f);
            if (bn + row < N)
                v = *reinterpret_cast<const float4*>(
                    &Bm[(size_t)(bn + row) * ldb + k0 + lcol]);
            Bs[lcol + 0][row] = v.x; Bs[lcol + 1][row] = v.y;
            Bs[lcol + 2][row] = v.z; Bs[lcol + 3][row] = v.w;
        }
        __syncthreads();
        #pragma unroll
        for (int kk = 0; kk < 16; kk++) {
            float a[8], b[8];
            *(float4*)&a[0] = *(const float4*)&As[kk][ty * 8];
            *(float4*)&a[4] = *(const float4*)&As[kk][ty * 8 + 4];
            *(float4*)&b[0] = *(const float4*)&Bs[kk][tx * 8];
            *(float4*)&b[4] = *(const float4*)&Bs[kk][tx * 8 + 4];
            #pragma unroll
            for (int i = 0; i < 8; i++)
                #pragma unroll
                for (int j = 0; j < 8; j++)
                    acc[i][j] = fmaf(a[i], b[j], acc[i][j]);
        }
        __syncthreads();
    }

    #pragma unroll
    for (int i = 0; i < 8; i++) {
        int r = bm + ty * 8 + i;
        #pragma unroll
        for (int jj = 0; jj < 8; jj += 4) {
            int c = bn + tx * 8 + jj;
            if (c + 3 < N) {
                float4 v;
                float* pv = &v.x;
                #pragma unroll
                for (int q = 0; q < 4; q++) {
                    float val = acc[i][jj + q];
                    if (EPI == 1) { val += bias[c + q]; val = fmaxf(val, 0.f) + log1pf(__expf(-fabsf(val))); }
                    if (EPI == 2) { val += bias[c + q]; val = val / (1.f + __expf(-val)); }
                    pv[q] = val;
                }
                *reinterpret_cast<float4*>(&C[(size_t)r * ldc + c]) = v;
            } else {
                #pragma unroll
                for (int q = 0; q < 4; q++) {
                    int cc = c + q;
                    if (cc < N) {
                        float val = acc[i][jj + q];
                        if (EPI == 1) { val += bias[cc]; val = fmaxf(val, 0.f) + log1pf(__expf(-fabsf(val))); }
                        if (EPI == 2) { val += bias[cc]; val = val / (1.f + __expf(-val)); }
                        C[(size_t)r * ldc + cc] = val;
                    }
                }
            }
        }
    }
}

// ---------------- causal depthwise conv(4) + SiLU ----------------
__global__ __launch_bounds__(256)
void conv_silu_kernel(const float* __restrict__ w, const float* __restrict__ bias)
{
    int idx = blockIdx.x * blockDim.x + threadIdx.x;
    if (idx >= MM * DI) return;
    int d = idx & (DI - 1);
    int m = idx >> 11;           // DI = 2048
    int l = m & (LL - 1);        // LL = 2048

    float acc = bias[d];
    const float w0 = w[d * 4 + 0], w1 = w[d * 4 + 1], w2 = w[d * 4 + 2], w3 = w[d * 4 + 3];
    const float* base = g_xz + (size_t)m * (2 * DI) + d;  // row m, xin part
    const ptrdiff_t rs = 2 * DI;
    if (l >= 3) {
        acc = fmaf(base[-3 * rs], w0, acc);
        acc = fmaf(base[-2 * rs], w1, acc);
        acc = fmaf(base[-1 * rs], w2, acc);
        acc = fmaf(base[0],       w3, acc);
    } else {
        if (l >= 3) acc = fmaf(base[-3 * rs], w0, acc);
        if (l >= 2) acc = fmaf(base[-2 * rs], w1, acc);
        if (l >= 1) acc = fmaf(base[-1 * rs], w2, acc);
        acc = fmaf(base[0], w3, acc);
    }
    float sig = 1.f / (1.f + __expf(-acc));
    g_xc[(size_t)m * DI + d] = acc * sig;
}

// ---------------- selective scan: lane-per-state, warp = 2 channels x 16 states ----------------
__global__ __launch_bounds__(256)
void scan_kernel(const float* __restrict__ A_log, const float* __restrict__ Dvec)
{
    const int tid  = threadIdx.x;
    const int warp = tid >> 5;
    const int lane = tid & 31;
    const int n = lane & 15;
    const int b = blockIdx.x >> 7;                              // 128 blocks / batch
    const int d = ((blockIdx.x & 127) << 4) + (warp << 1) + (lane >> 4);

    const float A  = -__expf(A_log[d * DS + n]);
    const float Dd = Dvec[d];
    float h = 0.f;

    const float* pd = g_delta + (size_t)b * LL * DI + d;
    const float* pu = g_xc    + (size_t)b * LL * DI + d;
    const float* pz = g_xz    + (size_t)b * LL * (2 * DI) + DI + d;
    const float* pb = g_xdbl  + (size_t)b * LL * NXD + DR + n;
    float*       py = g_y     + (size_t)b * LL * DI + d;

    #pragma unroll 2
    for (int t = 0; t < LL; t++) {
        const float delta = __ldg(pd);
        const float u     = __ldg(pu);
        const float Bn    = __ldg(pb);
        const float Cn    = __ldg(pb + DS);

        const float e = __expf(delta * A);
        h = fmaf(e, h, delta * u * Bn);

        float p = h * Cn;
        p += __shfl_xor_sync(0xffffffffu, p, 1);
        p += __shfl_xor_sync(0xffffffffu, p, 2);
        p += __shfl_xor_sync(0xffffffffu, p, 4);
        p += __shfl_xor_sync(0xffffffffu, p, 8);

        if (n == 0) {
            const float z = __ldg(pz);
            const float sig = 1.f / (1.f + __expf(-z));
            *py = (p + Dd * u) * (z * sig);
        }
        pd += DI; pu += DI; pz += 2 * DI; pb += NXD; py += DI;
    }
}

// ---------------- launch ----------------
extern "C" void kernel_launch(void* const* d_in, const int* in_sizes, int n_in,
                              void* d_out, int out_size)
{
    const float* x         = (const float*)d_in[0];
    const float* in_proj_w = (const float*)d_in[1];
    const float* conv_w    = (const float*)d_in[2];
    const float* conv_b    = (const float*)d_in[3];
    const float* x_proj_w  = (const float*)d_in[4];
    const float* dt_proj_w = (const float*)d_in[5];
    const float* dt_proj_b = (const float*)d_in[6];
    const float* A_log     = (const float*)d_in[7];
    const float* Dv        = (const float*)d_in[8];
    const float* ssm_out_w = (const float*)d_in[9];
    const float* final_w   = (const float*)d_in[10];
    const float* final_b   = (const float*)d_in[11];
    float* out = (float*)d_out;

    float *p_xz, *p_xc, *p_xdbl, *p_delta, *p_y, *p_o1;
    cudaGetSymbolAddress((void**)&p_xz,    g_xz);
    cudaGetSymbolAddress((void**)&p_xc,    g_xc);
    cudaGetSymbolAddress((void**)&p_xdbl,  g_xdbl);
    cudaGetSymbolAddress((void**)&p_delta, g_delta);
    cudaGetSymbolAddress((void**)&p_y,     g_y);
    cudaGetSymbolAddress((void**)&p_o1,    g_o1);

    // 1) in_proj: xz[4096,4096] = x[4096,1024] @ in_proj_w[4096,1024]^T
    sgemm_nt<0><<<dim3(32, 32), 256>>>(x, DM, in_proj_w, DM, p_xz, 2 * DI, 2 * DI, DM, nullptr);

    // 2) causal depthwise conv + SiLU -> g_xc
    conv_silu_kernel<<<(MM * DI) / 256, 256>>>(conv_w, conv_b);

    // 3a) x_dbl[4096,96] = xc @ x_proj_w[96,2048]^T
    sgemm_nt<0><<<dim3(1, 32), 256>>>(p_xc, DI, x_proj_w, DI, p_xdbl, NXD, NXD, DI, nullptr);

    // 3b) delta[4096,2048] = softplus(dt @ dt_proj_w[2048,64]^T + dt_proj_b)
    sgemm_nt<1><<<dim3(16, 32), 256>>>(p_xdbl, NXD, dt_proj_w, DR, p_delta, DI, DI, DR, dt_proj_b);

    // 4) selective scan + D-skip + SiLU(z) gate -> g_y
    scan_kernel<<<256, 256>>>(A_log, Dv);

    // 5) out_proj: o1[4096,1024] = y @ ssm_out_w[1024,2048]^T
    sgemm_nt<0><<<dim3(8, 32), 256>>>(p_y, DI, ssm_out_w, DI, p_o1, DM, DM, DI, nullptr);

    // 6) final: out = silu(o1 @ final_w[1024,1024]^T + final_b)
    sgemm_nt<2><<<dim3(8, 32), 256>>>(p_o1, DM, final_w, DM, out, DM, DM, DM, final_b);
}

// round 3
// speedup vs baseline: 1.3329x; 1.3329x over previous
#include <cuda_runtime.h>
#include <cuda_bf16.h>
#include <cstdint>
#include <math.h>

#define BB 2
#define LL 2048
#define DM 1024
#define DI 2048
#define DS 16
#define DR 64
#define NXD 96          // DR + 2*DS
#define MM (BB*LL)      // 4096

#define PAD_K 40        // bf16 elems per smem row (80 bytes) -> conflict-free ldmatrix

// ---------------- scratch (device globals: alloc-free) ----------------
__device__ float g_xz[(size_t)MM * (2*DI)];   // in_proj output: [xin | z]
__device__ float g_xc[(size_t)MM * DI];       // conv+silu output
__device__ float g_xdbl[(size_t)MM * NXD];    // [dt(64) | B(16) | C(16)]
__device__ float g_delta[(size_t)MM * DI];    // softplus(dt @ W + b)
__device__ float g_y[(size_t)MM * DI];        // gated scan output
__device__ float g_o1[(size_t)MM * DM];       // ssm out_proj output

// ---------------- mma.sync / ldmatrix helpers (sm_80+ portable) ----------------
__device__ __forceinline__ void mma_bf16(float* c, const uint32_t* a, const uint32_t* b) {
    asm volatile(
        "mma.sync.aligned.m16n8k16.row.col.f32.bf16.bf16.f32 "
        "{%0,%1,%2,%3}, {%4,%5,%6,%7}, {%8,%9}, {%0,%1,%2,%3};"
        : "+f"(c[0]), "+f"(c[1]), "+f"(c[2]), "+f"(c[3])
        : "r"(a[0]), "r"(a[1]), "r"(a[2]), "r"(a[3]), "r"(b[0]), "r"(b[1]));
}
__device__ __forceinline__ void ldsm_x4(uint32_t* r, uint32_t addr) {
    asm volatile("ldmatrix.sync.aligned.m8n8.x4.shared.b16 {%0,%1,%2,%3}, [%4];"
        : "=r"(r[0]), "=r"(r[1]), "=r"(r[2]), "=r"(r[3]) : "r"(addr));
}
__device__ __forceinline__ void ldsm_x2(uint32_t* r, uint32_t addr) {
    asm volatile("ldmatrix.sync.aligned.m8n8.x2.shared.b16 {%0,%1}, [%2];"
        : "=r"(r[0]), "=r"(r[1]) : "r"(addr));
}

__device__ __forceinline__ void cvt_store(char* hi, char* lo, float4 v) {
    float f[4] = {v.x, v.y, v.z, v.w};
    uint32_t hw[2], lw[2];
    #pragma unroll
    for (int i = 0; i < 2; i++) {
        __nv_bfloat16 h0 = __float2bfloat16_rn(f[2*i]);
        __nv_bfloat16 h1 = __float2bfloat16_rn(f[2*i+1]);
        float r0 = f[2*i]   - __bfloat162float(h0);
        float r1 = f[2*i+1] - __bfloat162float(h1);
        __nv_bfloat16 l0 = __float2bfloat16_rn(r0);
        __nv_bfloat16 l1 = __float2bfloat16_rn(r1);
        hw[i] = (uint32_t)__bfloat16_as_ushort(h0) | ((uint32_t)__bfloat16_as_ushort(h1) << 16);
        lw[i] = (uint32_t)__bfloat16_as_ushort(l0) | ((uint32_t)__bfloat16_as_ushort(l1) << 16);
    }
    *reinterpret_cast<uint2*>(hi) = make_uint2(hw[0], hw[1]);
    *reinterpret_cast<uint2*>(lo) = make_uint2(lw[0], lw[1]);
}

// ================= HMMA GEMM: C[M,N] = A[M,K](row) * B[N,K](row)^T =================
// bf16x3 split: D += Ah*Bh + Ah*Bl + Al*Bh (fp32 accumulate in HMMA)
// CTA tile 128x128, BK=32, 8 warps (warp tile 32x64), reg-prefetch pipeline.
// EPI: 0=none, 1=softplus(x+bias), 2=silu(x+bias)
template<int EPI>
__global__ __launch_bounds__(256, 1)
void hmma_gemm(const float* __restrict__ A, int lda,
               const float* __restrict__ Bm, int ldb,
               float* __restrict__ C, int ldc,
               int N, int K, const float* __restrict__ bias)
{
    __shared__ __align__(16) char smem[4 * 128 * PAD_K * 2];   // 40960 B
    char* sAh = smem;
    char* sAl = smem + 10240;
    char* sBh = smem + 20480;
    char* sBl = smem + 30720;
    const uint32_t su  = (uint32_t)__cvta_generic_to_shared(smem);
    const uint32_t suAh = su, suAl = su + 10240, suBh = su + 20480, suBl = su + 30720;

    const int tid  = threadIdx.x;
    const int wid  = tid >> 5;
    const int lane = tid & 31;
    const int bm = blockIdx.y * 128;
    const int bn = blockIdx.x * 128;
    const int warp_m = wid & 3;    // 0..3 -> 32 rows each
    const int warp_n = wid >> 2;   // 0..1 -> 64 cols each
    const int b_rows = min(128, N - bn);

    float acc[2][8][4];
    #pragma unroll
    for (int i = 0; i < 2; i++)
        #pragma unroll
        for (int j = 0; j < 8; j++)
            #pragma unroll
            for (int q = 0; q < 4; q++) acc[i][j][q] = 0.f;

    // staging coords: thread -> (row 0..31 step +32 x4, col4)
    const int s_row = tid >> 3;
    const int s_c4  = (tid & 7) << 2;

    float4 ra[4], rb[4];
    // prologue load chunk 0
    {
        #pragma unroll
        for (int i = 0; i < 4; i++) {
            int r = s_row + i * 32;
            ra[i] = *reinterpret_cast<const float4*>(&A[(size_t)(bm + r) * lda + s_c4]);
            rb[i] = (r < b_rows)
                ? *reinterpret_cast<const float4*>(&Bm[(size_t)(bn + r) * ldb + s_c4])
                : make_float4(0.f, 0.f, 0.f, 0.f);
        }
    }

    const int nch = K >> 5;
    for (int c = 0; c < nch; c++) {
        // store staged chunk to smem (hi/lo split)
        #pragma unroll
        for (int i = 0; i < 4; i++) {
            int r = s_row + i * 32;
            uint32_t off = (uint32_t)(r * (PAD_K * 2) + s_c4 * 2);
            cvt_store(sAh + off, sAl + off, ra[i]);
            cvt_store(sBh + off, sBl + off, rb[i]);
        }
        __syncthreads();

        // prefetch next chunk (overlaps with HMMA below)
        if (c + 1 < nch) {
            const int k0 = (c + 1) << 5;
            #pragma unroll
            for (int i = 0; i < 4; i++) {
                int r = s_row + i * 32;
                ra[i] = *reinterpret_cast<const float4*>(&A[(size_t)(bm + r) * lda + k0 + s_c4]);
                rb[i] = (r < b_rows)
                    ? *reinterpret_cast<const float4*>(&Bm[(size_t)(bn + r) * ldb + k0 + s_c4])
                    : make_float4(0.f, 0.f, 0.f, 0.f);
            }
        }

        #pragma unroll
        for (int ks = 0; ks < 2; ks++) {
            uint32_t ah[2][4], al[2][4];
            #pragma unroll
            for (int mt = 0; mt < 2; mt++) {
                const uint32_t ro = (uint32_t)(((warp_m * 32 + mt * 16 + (lane & 15)) * PAD_K
                                     + ks * 16 + ((lane >> 4) << 3)) * 2);
                ldsm_x4(ah[mt], suAh + ro);
                ldsm_x4(al[mt], suAl + ro);
            }
            #pragma unroll
            for (int nt = 0; nt < 8; nt++) {
                const uint32_t bo = (uint32_t)(((warp_n * 64 + nt * 8 + (lane & 7)) * PAD_K
                                     + ks * 16 + (((lane >> 3) & 1) << 3)) * 2);
                uint32_t bh[2], bl[2];
                ldsm_x2(bh, suBh + bo);
                ldsm_x2(bl, suBl + bo);
                #pragma unroll
                for (int mt = 0; mt < 2; mt++) {
                    mma_bf16(acc[mt][nt], ah[mt], bh);
                    mma_bf16(acc[mt][nt], ah[mt], bl);
                    mma_bf16(acc[mt][nt], al[mt], bh);
                }
            }
        }
        __syncthreads();
    }

    // epilogue: lane l holds (row l/4, col 2*(l%4)+{0,1}) and (row l/4+8, ...)
    #pragma unroll
    for (int mt = 0; mt < 2; mt++) {
        const int r0 = bm + warp_m * 32 + mt * 16 + (lane >> 2);
        #pragma unroll
        for (int nt = 0; nt < 8; nt++) {
            const int col = bn + warp_n * 64 + nt * 8 + ((lane & 3) << 1);
            if (col < N) {
                float v[4];
                #pragma unroll
                for (int q = 0; q < 4; q++) {
                    float val = acc[mt][nt][q];
                    if (EPI == 1) {
                        val += bias[col + (q & 1)];
                        val = fmaxf(val, 0.f) + log1pf(__expf(-fabsf(val)));
                    }
                    if (EPI == 2) {
                        val += bias[col + (q & 1)];
                        val = val / (1.f + __expf(-val));
                    }
                    v[q] = val;
                }
                *reinterpret_cast<float2*>(&C[(size_t)r0 * ldc + col]) = make_float2(v[0], v[1]);
                *reinterpret_cast<float2*>(&C[(size_t)(r0 + 8) * ldc + col]) = make_float2(v[2], v[3]);
            }
        }
    }
}

// ---------------- causal depthwise conv(4) + SiLU ----------------
__global__ __launch_bounds__(256)
void conv_silu_kernel(const float* __restrict__ w, const float* __restrict__ bias)
{
    int idx = blockIdx.x * blockDim.x + threadIdx.x;
    if (idx >= MM * DI) return;
    int d = idx & (DI - 1);
    int m = idx >> 11;
    int l = m & (LL - 1);

    float acc = bias[d];
    const float w0 = w[d * 4 + 0], w1 = w[d * 4 + 1], w2 = w[d * 4 + 2], w3 = w[d * 4 + 3];
    const float* base = g_xz + (size_t)m * (2 * DI) + d;
    const ptrdiff_t rs = 2 * DI;
    if (l >= 3) acc = fmaf(base[-3 * rs], w0, acc);
    if (l >= 2) acc = fmaf(base[-2 * rs], w1, acc);
    if (l >= 1) acc = fmaf(base[-1 * rs], w2, acc);
    acc = fmaf(base[0], w3, acc);
    float sig = 1.f / (1.f + __expf(-acc));
    g_xc[(size_t)m * DI + d] = acc * sig;
}

// ---------------- selective scan: lane-per-state ----------------
__global__ __launch_bounds__(256)
void scan_kernel(const float* __restrict__ A_log, const float* __restrict__ Dvec)
{
    const int tid  = threadIdx.x;
    const int warp = tid >> 5;
    const int lane = tid & 31;
    const int n = lane & 15;
    const int b = blockIdx.x >> 7;
    const int d = ((blockIdx.x & 127) << 4) + (warp << 1) + (lane >> 4);

    const float A  = -__expf(A_log[d * DS + n]);
    const float Dd = Dvec[d];
    float h = 0.f;

    const float* pd = g_delta + (size_t)b * LL * DI + d;
    const float* pu = g_xc    + (size_t)b * LL * DI + d;
    const float* pz = g_xz    + (size_t)b * LL * (2 * DI) + DI + d;
    const float* pb = g_xdbl  + (size_t)b * LL * NXD + DR + n;
    float*       py = g_y     + (size_t)b * LL * DI + d;

    #pragma unroll 2
    for (int t = 0; t < LL; t++) {
        const float delta = __ldg(pd);
        const float u     = __ldg(pu);
        const float Bn    = __ldg(pb);
        const float Cn    = __ldg(pb + DS);

        const float e = __expf(delta * A);
        h = fmaf(e, h, delta * u * Bn);

        float p = h * Cn;
        p += __shfl_xor_sync(0xffffffffu, p, 1);
        p += __shfl_xor_sync(0xffffffffu, p, 2);
        p += __shfl_xor_sync(0xffffffffu, p, 4);
        p += __shfl_xor_sync(0xffffffffu, p, 8);

        if (n == 0) {
            const float z = __ldg(pz);
            const float sig = 1.f / (1.f + __expf(-z));
            *py = (p + Dd * u) * (z * sig);
        }
        pd += DI; pu += DI; pz += 2 * DI; pb += NXD; py += DI;
    }
}

// ---------------- launch ----------------
extern "C" void kernel_launch(void* const* d_in, const int* in_sizes, int n_in,
                              void* d_out, int out_size)
{
    const float* x         = (const float*)d_in[0];
    const float* in_proj_w = (const float*)d_in[1];
    const float* conv_w    = (const float*)d_in[2];
    const float* conv_b    = (const float*)d_in[3];
    const float* x_proj_w  = (const float*)d_in[4];
    const float* dt_proj_w = (const float*)d_in[5];
    const float* dt_proj_b = (const float*)d_in[6];
    const float* A_log     = (const float*)d_in[7];
    const float* Dv        = (const float*)d_in[8];
    const float* ssm_out_w = (const float*)d_in[9];
    const float* final_w   = (const float*)d_in[10];
    const float* final_b   = (const float*)d_in[11];
    float* out = (float*)d_out;

    float *p_xz, *p_xc, *p_xdbl, *p_delta, *p_y, *p_o1;
    cudaGetSymbolAddress((void**)&p_xz,    g_xz);
    cudaGetSymbolAddress((void**)&p_xc,    g_xc);
    cudaGetSymbolAddress((void**)&p_xdbl,  g_xdbl);
    cudaGetSymbolAddress((void**)&p_delta, g_delta);
    cudaGetSymbolAddress((void**)&p_y,     g_y);
    cudaGetSymbolAddress((void**)&p_o1,    g_o1);

    // 1) in_proj: xz[4096,4096] = x[4096,1024] @ in_proj_w[4096,1024]^T
    hmma_gemm<0><<<dim3(32, 32), 256>>>(x, DM, in_proj_w, DM, p_xz, 2*DI, 2*DI, DM, nullptr);

    // 2) causal depthwise conv + SiLU -> g_xc
    conv_silu_kernel<<<(MM * DI) / 256, 256>>>(conv_w, conv_b);

    // 3a) x_dbl[4096,96] = xc @ x_proj_w[96,2048]^T
    hmma_gemm<0><<<dim3(1, 32), 256>>>(p_xc, DI, x_proj_w, DI, p_xdbl, NXD, NXD, DI, nullptr);

    // 3b) delta[4096,2048] = softplus(dt @ dt_proj_w[2048,64]^T + dt_proj_b)
    hmma_gemm<1><<<dim3(16, 32), 256>>>(p_xdbl, NXD, dt_proj_w, DR, p_delta, DI, DI, DR, dt_proj_b);

    // 4) selective scan + D-skip + SiLU(z) gate -> g_y
    scan_kernel<<<256, 256>>>(A_log, Dv);

    // 5) out_proj: o1[4096,1024] = y @ ssm_out_w[1024,2048]^T
    hmma_gemm<0><<<dim3(8, 32), 256>>>(p_y, DI, ssm_out_w, DI, p_o1, DM, DM, DI, nullptr);

    // 6) final: out = silu(o1 @ final_w[1024,1024]^T + final_b)
    hmma_gemm<2><<<dim3(8, 32), 256>>>(p_o1, DM, final_w, DM, out, DM, DM, DM, final_b);
}